// round 9
// baseline (speedup 1.0000x reference)
#include <cuda_runtime.h>
#include <cuda_bf16.h>
#include <math.h>

#define N_NODES 8192
#define HIDDEN  256
#define HEADS   4
#define HEAD_DIM 64
#define NUM_EDGES 4096
#define NUM_INC 65536
#define LN_EPS 1e-5f

// ---------------- scratch (device globals; no allocation allowed) -------------
__device__ float4   g_u4[HIDDEN];              // folded W_w x edge_att, [j].h
__device__ float    g_c[HEADS];                // folded W_b x edge_att
__device__ float4   g_logit[N_NODES];          // per-node logits, 4 heads
__device__ float4   g_expv[NUM_INC];           // exp(logit) cached per incidence
__device__ float    g_segsum[NUM_EDGES * HEADS];
__device__ float4   g_rseg[NUM_EDGES];         // valid ? 0.25/segsum : 0
__device__ int      g_ecount[NUM_EDGES];
__device__ int      g_eoffset[NUM_EDGES];
__device__ int      g_epos[NUM_EDGES];
__device__ float    g_snode[N_NODES];
__device__ int      g_cnode[N_NODES];
__device__ int      g_noffset[N_NODES];
__device__ int      g_npos[N_NODES];
__device__ int      g_sorted_node[NUM_INC];    // edge-CSR: member node ids
__device__ int      g_ne[NUM_INC];             // node-CSR: edge id per incidence
__device__ float    g_na[NUM_INC];             // node-CSR: attn_mean per incidence
__device__ float    g_y[N_NODES * HIDDEN];     // x @ out_w^T

// ---------------- K0: init scratch + fold weights (last block) ----------------
__global__ void k_init_prep(const float* __restrict__ W_w, const float* __restrict__ W_b,
                            const float* __restrict__ edge_att) {
    if (blockIdx.x == gridDim.x - 1) {
        __shared__ float ea[HEADS * HEAD_DIM];
        int j = threadIdx.x;
        ea[j] = edge_att[j];
        __syncthreads();
        float acc[HEADS];
        #pragma unroll
        for (int h = 0; h < HEADS; h++) {
            float s = 0.f;
            #pragma unroll 8
            for (int d = 0; d < HEAD_DIM; d++)
                s += W_w[(h * HEAD_DIM + d) * HIDDEN + j] * ea[h * HEAD_DIM + d];
            acc[h] = s;
        }
        g_u4[j] = make_float4(acc[0], acc[1], acc[2], acc[3]);
        if (j < HEADS) {
            float s = 0.f;
            for (int d = 0; d < HEAD_DIM; d++)
                s += W_b[j * HEAD_DIM + d] * ea[j * HEAD_DIM + d];
            g_c[j] = s;
        }
        return;
    }
    int i = blockIdx.x * blockDim.x + threadIdx.x;
    if (i < NUM_EDGES * HEADS) g_segsum[i] = 0.f;
    if (i < NUM_EDGES) { g_ecount[i] = 0; g_epos[i] = 0; }
    if (i < N_NODES) { g_snode[i] = 0.f; g_cnode[i] = 0; g_npos[i] = 0; }
}

// ---------------- K1: per-node logits (one warp per node) ---------------------
__global__ void k_logit(const float* __restrict__ x) {
    int warp = (blockIdx.x * blockDim.x + threadIdx.x) >> 5;
    int lane = threadIdx.x & 31;
    if (warp >= N_NODES) return;
    const float* xr = x + (size_t)warp * HIDDEN;
    float s0 = 0.f, s1 = 0.f, s2 = 0.f, s3 = 0.f;
    #pragma unroll
    for (int t = 0; t < 8; t++) {
        float xv = __ldg(xr + lane + 32 * t);
        float4 u = g_u4[lane + 32 * t];
        s0 += xv * u.x; s1 += xv * u.y; s2 += xv * u.z; s3 += xv * u.w;
    }
    #pragma unroll
    for (int off = 16; off; off >>= 1) {
        s0 += __shfl_xor_sync(0xffffffffu, s0, off);
        s1 += __shfl_xor_sync(0xffffffffu, s1, off);
        s2 += __shfl_xor_sync(0xffffffffu, s2, off);
        s3 += __shfl_xor_sync(0xffffffffu, s3, off);
    }
    if (lane == 0)
        g_logit[warp] = make_float4(s0 + g_c[0], s1 + g_c[1], s2 + g_c[2], s3 + g_c[3]);
}

// ---------------- K2: pass1 — one thread per (incidence, head) ----------------
// Softmax shift removed: logits are bounded, exp is safe, and p/segsum is
// analytically identical to the max-subtracted reference.
__global__ void k_pass1(const int* __restrict__ node_idx, const int* __restrict__ edge_idx) {
    int t = blockIdx.x * blockDim.x + threadIdx.x;
    if (t >= NUM_INC * HEADS) return;
    int i = t >> 2, h = t & 3;
    int n = node_idx[i], e = edge_idx[i];
    float l = ((const float*)g_logit)[n * HEADS + h];
    float p = expf(l);
    ((float*)g_expv)[t] = p;
    atomicAdd(&g_segsum[e * HEADS + h], p);
    if (h == 0) {
        atomicAdd(&g_ecount[e], 1);
        atomicAdd(&g_cnode[n], 1);
    }
}

// ---------------- K3: scans — block 0: edges(+rseg), block 1: nodes -----------
__global__ void k_scan() {
    __shared__ int sh[1024];
    int t = threadIdx.x;
    if (blockIdx.x == 0) {
        int local[4];
        int s = 0;
        #pragma unroll
        for (int i = 0; i < 4; i++) { local[i] = g_ecount[t * 4 + i]; s += local[i]; }
        sh[t] = s;
        __syncthreads();
        for (int off = 1; off < 1024; off <<= 1) {
            int add = (t >= off) ? sh[t - off] : 0;
            __syncthreads();
            sh[t] += add;
            __syncthreads();
        }
        int excl = sh[t] - s;
        #pragma unroll
        for (int i = 0; i < 4; i++) {
            int e = t * 4 + i;
            g_eoffset[e] = excl; excl += local[i];
            float4 r;
            if (local[i] >= 2) {
                r.x = 0.25f / g_segsum[e * HEADS + 0];
                r.y = 0.25f / g_segsum[e * HEADS + 1];
                r.z = 0.25f / g_segsum[e * HEADS + 2];
                r.w = 0.25f / g_segsum[e * HEADS + 3];
            } else {
                r = make_float4(0.f, 0.f, 0.f, 0.f);
            }
            g_rseg[e] = r;
        }
    } else {
        int local[8];
        int s = 0;
        #pragma unroll
        for (int i = 0; i < 8; i++) { local[i] = g_cnode[t * 8 + i]; s += local[i]; }
        sh[t] = s;
        __syncthreads();
        for (int off = 1; off < 1024; off <<= 1) {
            int add = (t >= off) ? sh[t - off] : 0;
            __syncthreads();
            sh[t] += add;
            __syncthreads();
        }
        int excl = sh[t] - s;
        #pragma unroll
        for (int i = 0; i < 8; i++) { g_noffset[t * 8 + i] = excl; excl += local[i]; }
    }
}

// ---------------- K4: pass2 — attn_mean, node sums, both CSR scatters ---------
__global__ void k_pass2(const int* __restrict__ node_idx, const int* __restrict__ edge_idx) {
    int i = blockIdx.x * blockDim.x + threadIdx.x;
    if (i >= NUM_INC) return;
    int n = node_idx[i], e = edge_idx[i];
    float4 p = g_expv[i];
    float4 r = g_rseg[e];
    float am = p.x * r.x + p.y * r.y + p.z * r.z + p.w * r.w;
    atomicAdd(&g_snode[n], am);
    // edge-CSR (members of each edge)
    int pos = atomicAdd(&g_epos[e], 1);
    g_sorted_node[g_eoffset[e] + pos] = n;
    // node-CSR (edges of each node, with attn)
    int pos2 = atomicAdd(&g_npos[n], 1);
    int nidx = g_noffset[n] + pos2;
    g_ne[nidx] = e;
    g_na[nidx] = am;
}

// ---------------- K5: fp32 GEMM  y = x @ out_w^T ------------------------------
__global__ void k_gemm(const float* __restrict__ X, const float* __restrict__ W) {
    __shared__ float As[16][64];
    __shared__ float Ws[16][64];
    int m0 = blockIdx.y * 64;
    int n0 = blockIdx.x * 64;
    int tid = threadIdx.x;
    int tx = tid & 15;
    int ty = tid >> 4;
    int lr = tid >> 2;
    int lk = (tid & 3) * 4;

    float acc[4][4];
    #pragma unroll
    for (int i = 0; i < 4; i++)
        #pragma unroll
        for (int j = 0; j < 4; j++) acc[i][j] = 0.f;

    for (int kt = 0; kt < HIDDEN; kt += 16) {
        float4 av = *(const float4*)&X[(size_t)(m0 + lr) * HIDDEN + kt + lk];
        float4 wv = *(const float4*)&W[(size_t)(n0 + lr) * HIDDEN + kt + lk];
        As[lk + 0][lr] = av.x; As[lk + 1][lr] = av.y; As[lk + 2][lr] = av.z; As[lk + 3][lr] = av.w;
        Ws[lk + 0][lr] = wv.x; Ws[lk + 1][lr] = wv.y; Ws[lk + 2][lr] = wv.z; Ws[lk + 3][lr] = wv.w;
        __syncthreads();
        #pragma unroll
        for (int kk = 0; kk < 16; kk++) {
            float a[4], b[4];
            #pragma unroll
            for (int i = 0; i < 4; i++) a[i] = As[kk][ty * 4 + i];
            #pragma unroll
            for (int j = 0; j < 4; j++) b[j] = Ws[kk][tx * 4 + j];
            #pragma unroll
            for (int i = 0; i < 4; i++)
                #pragma unroll
                for (int j = 0; j < 4; j++) acc[i][j] += a[i] * b[j];
        }
        __syncthreads();
    }
    #pragma unroll
    for (int i = 0; i < 4; i++) {
        float4 v = make_float4(acc[i][0], acc[i][1], acc[i][2], acc[i][3]);
        *(float4*)&g_y[(size_t)(m0 + ty * 4 + i) * HIDDEN + n0 + tx * 4] = v;
    }
}

// ---------------- K6: scale + bias + LayerNorm --------------------------------
__global__ void k_ln(const float* __restrict__ out_b, float* __restrict__ out) {
    int n = blockIdx.x;
    int t = threadIdx.x;
    int lane = t & 31, wid = t >> 5;
    __shared__ float sh[8];
    float alpha = g_snode[n] / fmaxf((float)g_cnode[n], 1.0f);
    float v = alpha * g_y[(size_t)n * HIDDEN + t] + out_b[t];

    float s = v;
    #pragma unroll
    for (int off = 16; off; off >>= 1) s += __shfl_xor_sync(0xffffffffu, s, off);
    if (lane == 0) sh[wid] = s;
    __syncthreads();
    float tot = 0.f;
    #pragma unroll
    for (int w = 0; w < 8; w++) tot += sh[w];
    float mu = tot * (1.0f / HIDDEN);
    __syncthreads();

    float d = v - mu;
    float s2 = d * d;
    #pragma unroll
    for (int off = 16; off; off >>= 1) s2 += __shfl_xor_sync(0xffffffffu, s2, off);
    if (lane == 0) sh[wid] = s2;
    __syncthreads();
    float tot2 = 0.f;
    #pragma unroll
    for (int w = 0; w < 8; w++) tot2 += sh[w];
    float var = tot2 * (1.0f / HIDDEN);

    out[(size_t)n * HIDDEN + t] = d * rsqrtf(var + LN_EPS);
}

// ---------------- K7: AW row construction — one block per node row ------------
// Builds AW[i,:] in a 32KB SMEM row (no zero prepass, no global atomics),
// then streams it to GMEM once. DRAM traffic = exactly one 256MB write.
__global__ __launch_bounds__(256) void k_aw_row(float* __restrict__ AW) {
    __shared__ float row[N_NODES];                 // 32 KB
    int i = blockIdx.x;
    float4* r4 = (float4*)row;
    float4 z = make_float4(0.f, 0.f, 0.f, 0.f);
    #pragma unroll
    for (int t = threadIdx.x; t < N_NODES / 4; t += 256) r4[t] = z;
    __syncthreads();

    int beg = g_noffset[i];
    int cnt = g_cnode[i];
    int warp = threadIdx.x >> 5, lane = threadIdx.x & 31;
    for (int k = warp; k < cnt; k += 8) {          // one warp per incident edge
        int e = g_ne[beg + k];
        float am = g_na[beg + k];
        if (am != 0.f) {
            int mb = g_eoffset[e], m = g_ecount[e];
            for (int t = lane; t < m; t += 32)
                atomicAdd(&row[g_sorted_node[mb + t]], am);
        }
    }
    __syncthreads();
    if (threadIdx.x == 0) row[i] = 0.f;            // zero diagonal
    __syncthreads();

    float4* o4 = (float4*)(AW + (size_t)i * N_NODES);
    #pragma unroll
    for (int t = threadIdx.x; t < N_NODES / 4; t += 256)
        __stcs(&o4[t], r4[t]);
}

// ---------------- launch ------------------------------------------------------
static cudaStream_t s_gemm = nullptr;
static cudaEvent_t ev_fork = nullptr, ev_gemm = nullptr;

extern "C" void kernel_launch(void* const* d_in, const int* in_sizes, int n_in,
                              void* d_out, int out_size) {
    const float* x        = (const float*)d_in[0];
    const int*   node_idx = (const int*)d_in[1];
    const int*   edge_idx = (const int*)d_in[2];
    const float* W_w      = (const float*)d_in[3];
    const float* W_b      = (const float*)d_in[4];
    const float* edge_att = (const float*)d_in[5];
    const float* out_w    = (const float*)d_in[6];
    const float* out_b    = (const float*)d_in[7];

    float* out = (float*)d_out;                         // [8192, 256]
    float* AW  = out + (size_t)N_NODES * HIDDEN;        // [8192, 8192]

    if (s_gemm == nullptr) {
        cudaStreamCreateWithFlags(&s_gemm, cudaStreamNonBlocking);
        cudaEventCreateWithFlags(&ev_fork, cudaEventDisableTiming);
        cudaEventCreateWithFlags(&ev_gemm, cudaEventDisableTiming);
    }

    // fork GEMM stream off the capture-origin stream
    cudaEventRecord(ev_fork, 0);
    cudaStreamWaitEvent(s_gemm, ev_fork, 0);

    // side stream: independent dense GEMM (overlaps the incidence chain)
    k_gemm<<<dim3(HIDDEN / 64, N_NODES / 64), 256, 0, s_gemm>>>(x, out_w);
    cudaEventRecord(ev_gemm, s_gemm);

    // main chain: incidence processing
    k_init_prep<<<64 + 1, 256>>>(W_w, W_b, edge_att);
    k_logit<<<N_NODES * 32 / 256, 256>>>(x);
    k_pass1<<<NUM_INC * HEADS / 256, 256>>>(node_idx, edge_idx);
    k_scan<<<2, 1024>>>();
    k_pass2<<<NUM_INC / 256, 256>>>(node_idx, edge_idx);

    // LN (needs gemm + pass2), then the big AW row write
    cudaStreamWaitEvent(0, ev_gemm, 0);
    k_ln<<<N_NODES, HIDDEN>>>(out_b, out);
    k_aw_row<<<N_NODES, 256>>>(AW);
}